// round 12
// baseline (speedup 1.0000x reference)
#include <cuda_runtime.h>
#include <cuda_bf16.h>

#define BATCH 16384
#define VOCAB 100000
#define EMBED 300
#define NCTX  10
#define NNEG  20
#define NSC   (1 + NNEG)   // 21 scores
#define NF4   75           // 300 floats = 75 float4 slots per row
#define WARPS_PER_BLOCK 8
#define BLOCK_THREADS   (WARPS_PER_BLOCK * 32)
#define GRID_BLOCKS     (BATCH / WARPS_PER_BLOCK)   // 2048
#define MIN_BLOCKS_SM   6
#define VHALF (VOCAB / 2)

// context means, bf16-packed (600 B per b = 75 uint2; 9.83 MB)
__device__ uint2 g_cm[BATCH * NF4];
// partial scores across cen vocab halves (1.37 MB)
__device__ float g_acc[BATCH * NSC];
// fused-reduction state (zero-init .bss; last block resets for graph replays)
__device__ float        g_sum;
__device__ unsigned int g_arrived;

__device__ __forceinline__ float log_sigmoid(float x) {
    return fminf(x, 0.0f) - log1pf(__expf(-fabsf(x)));
}
__device__ __forceinline__ float dot4(float4 a, float4 b) {
    return a.x * b.x + a.y * b.y + a.z * b.z + a.w * b.w;
}
__device__ __forceinline__ uint2 pack_bf16x4(float4 v) {
    __nv_bfloat162 lo = __float22bfloat162_rn(make_float2(v.x, v.y));
    __nv_bfloat162 hi = __float22bfloat162_rn(make_float2(v.z, v.w));
    uint2 r;
    r.x = *reinterpret_cast<unsigned int*>(&lo);
    r.y = *reinterpret_cast<unsigned int*>(&hi);
    return r;
}
__device__ __forceinline__ float4 unpack_bf16x4(uint2 p) {
    __nv_bfloat162 lo = *reinterpret_cast<__nv_bfloat162*>(&p.x);
    __nv_bfloat162 hi = *reinterpret_cast<__nv_bfloat162*>(&p.y);
    float2 a = __bfloat1622float2(lo);
    float2 b = __bfloat1622float2(hi);
    return make_float4(a.x, a.y, b.x, b.y);
}

// ───────────── Pass A: ctx gathers → bf16 cm (WS ~97 MB) ─────────────
__global__ __launch_bounds__(BLOCK_THREADS, MIN_BLOCKS_SM)
void cbow_ctx_mean_kernel(const int*   __restrict__ context,
                          const float* __restrict__ ctx_w)
{
    const int warp = threadIdx.x >> 5;
    const int lane = threadIdx.x & 31;
    const int b    = blockIdx.x * WARPS_PER_BLOCK + warp;

    int idx = 0;
    if (lane < NCTX) idx = context[b * NCTX + lane];

    float4 cm0 = make_float4(0.f, 0.f, 0.f, 0.f);
    float4 cm1 = cm0;
    float4 cm2 = cm0;
    const bool tail = (lane < NF4 - 64);

    #pragma unroll
    for (int c = 0; c < NCTX; ++c) {
        int row = __shfl_sync(0xffffffffu, idx, c);
        const float4* r = reinterpret_cast<const float4*>(ctx_w + (size_t)row * EMBED);
        float4 a0 = __ldg(r + lane);
        float4 a1 = __ldg(r + lane + 32);
        cm0.x += a0.x; cm0.y += a0.y; cm0.z += a0.z; cm0.w += a0.w;
        cm1.x += a1.x; cm1.y += a1.y; cm1.z += a1.z; cm1.w += a1.w;
        if (tail) {
            float4 a2 = __ldg(r + lane + 64);
            cm2.x += a2.x; cm2.y += a2.y; cm2.z += a2.z; cm2.w += a2.w;
        }
    }
    const float inv_c = 1.0f / (float)NCTX;
    cm0.x *= inv_c; cm0.y *= inv_c; cm0.z *= inv_c; cm0.w *= inv_c;
    cm1.x *= inv_c; cm1.y *= inv_c; cm1.z *= inv_c; cm1.w *= inv_c;
    cm2.x *= inv_c; cm2.y *= inv_c; cm2.z *= inv_c; cm2.w *= inv_c;

    uint2* dst = g_cm + (size_t)b * NF4;
    dst[lane]      = pack_bf16x4(cm0);
    dst[lane + 32] = pack_bf16x4(cm1);
    if (tail) dst[lane + 64] = pack_bf16x4(cm2);
}

// ───────────── Pass B: cen gathers restricted to [lo, hi) ─────────────
template <bool LAST>
__global__ __launch_bounds__(BLOCK_THREADS, MIN_BLOCKS_SM)
void cbow_score_half_kernel(const int*   __restrict__ center,
                            const int*   __restrict__ negatives,
                            const float* __restrict__ cen_w,
                            float*       __restrict__ out,
                            int lo, int hi)
{
    const int warp = threadIdx.x >> 5;
    const int lane = threadIdx.x & 31;
    const int b    = blockIdx.x * WARPS_PER_BLOCK + warp;

    int idx = 0;
    if (lane == 0)         idx = center[b];
    else if (lane <= NNEG) idx = negatives[b * NNEG + (lane - 1)];

    const uint2* src = g_cm + (size_t)b * NF4;
    const bool tail = (lane < NF4 - 64);
    float4 cm0 = unpack_bf16x4(src[lane]);
    float4 cm1 = unpack_bf16x4(src[lane + 32]);
    float4 cm2 = tail ? unpack_bf16x4(src[lane + 64])
                      : make_float4(0.f, 0.f, 0.f, 0.f);

    __shared__ float sh_s[WARPS_PER_BLOCK][NSC];

    #pragma unroll
    for (int t = 0; t < NSC; ++t) {
        int row = __shfl_sync(0xffffffffu, idx, t);
        float s = 0.0f;
        if (row >= lo && row < hi) {            // warp-uniform branch
            const float4* r = reinterpret_cast<const float4*>(cen_w + (size_t)row * EMBED);
            float4 a0 = __ldg(r + lane);
            float4 a1 = __ldg(r + lane + 32);
            s = dot4(a0, cm0) + dot4(a1, cm1);
            if (tail) {
                float4 a2 = __ldg(r + lane + 64);
                s += dot4(a2, cm2);
            }
            #pragma unroll
            for (int off = 16; off > 0; off >>= 1)
                s += __shfl_xor_sync(0xffffffffu, s, off);
        }
        if (lane == 0) sh_s[warp][t] = s;
    }
    __syncwarp();

    if (!LAST) {
        // first half: write partial scores
        if (lane < NSC) g_acc[b * NSC + lane] = sh_s[warp][lane];
        return;
    }

    // last half: combine, log-sigmoid per lane, reduce, finalize
    float l = 0.0f;
    if (lane < NSC) {
        float s = g_acc[b * NSC + lane] + sh_s[warp][lane];
        l = log_sigmoid(lane == 0 ? s : -s);
    }
    #pragma unroll
    for (int off = 16; off > 0; off >>= 1)
        l += __shfl_xor_sync(0xffffffffu, l, off);

    __shared__ float sdata[WARPS_PER_BLOCK];
    if (lane == 0) sdata[warp] = -l;
    __syncthreads();

    if (threadIdx.x == 0) {
        float tot = 0.f;
        #pragma unroll
        for (int i = 0; i < WARPS_PER_BLOCK; ++i) tot += sdata[i];

        atomicAdd(&g_sum, tot);
        __threadfence();
        unsigned prev = atomicAdd(&g_arrived, 1u);
        if (prev == GRID_BLOCKS - 1) {
            float total = g_sum;
            out[0] = total / (float)BATCH;
            g_sum = 0.0f;
            __threadfence();
            g_arrived = 0u;
        }
    }
}

extern "C" void kernel_launch(void* const* d_in, const int* in_sizes, int n_in,
                              void* d_out, int out_size)
{
    const int*   context   = (const int*)  d_in[0];
    const int*   center    = (const int*)  d_in[1];
    const int*   negatives = (const int*)  d_in[2];
    const float* ctx_w     = (const float*)d_in[3];
    const float* cen_w     = (const float*)d_in[4];
    float*       out       = (float*)d_out;

    cbow_ctx_mean_kernel<<<GRID_BLOCKS, BLOCK_THREADS>>>(context, ctx_w);
    cbow_score_half_kernel<false><<<GRID_BLOCKS, BLOCK_THREADS>>>(
        center, negatives, cen_w, out, 0, VHALF);
    cbow_score_half_kernel<true><<<GRID_BLOCKS, BLOCK_THREADS>>>(
        center, negatives, cen_w, out, VHALF, VOCAB);
}

// round 13
// speedup vs baseline: 1.1014x; 1.1014x over previous
#include <cuda_runtime.h>

#define BATCH 16384
#define EMBED 300
#define NCTX  10
#define NNEG  20
#define NSC   (1 + NNEG)   // 21 scores
#define NF4   75           // 300 floats = 75 float4 slots per row
#define WARPS_PER_BLOCK 8
#define BLOCK_THREADS   (WARPS_PER_BLOCK * 32)
#define GRID_BLOCKS     (BATCH / WARPS_PER_BLOCK)   // 2048
#define MIN_BLOCKS_SM   4     // 64-reg budget: room for pipelined loads

// fused-reduction state (zero-init .bss; last block resets for graph replays)
__device__ float        g_sum;
__device__ unsigned int g_arrived;

__device__ __forceinline__ float log_sigmoid(float x) {
    return fminf(x, 0.0f) - log1pf(__expf(-fabsf(x)));
}
__device__ __forceinline__ float dot4(float4 a, float4 b) {
    return a.x * b.x + a.y * b.y + a.z * b.z + a.w * b.w;
}

// ctx rows: stream through L2 (lose the LRU race to cen rows)
__device__ __forceinline__ unsigned long long policy_evict_first() {
    unsigned long long p;
    asm("createpolicy.fractional.L2::evict_first.b64 %0, 1.0;" : "=l"(p));
    return p;
}
// cen rows: pin half the accesses in the evict_last class
__device__ __forceinline__ unsigned long long policy_evict_last_half() {
    unsigned long long p;
    asm("createpolicy.fractional.L2::evict_last.b64 %0, 0.5;" : "=l"(p));
    return p;
}
__device__ __forceinline__ float4 ldg_hint(const float4* p, unsigned long long pol) {
    float4 v;
    asm("ld.global.nc.L2::cache_hint.v4.f32 {%0,%1,%2,%3}, [%4], %5;"
        : "=f"(v.x), "=f"(v.y), "=f"(v.z), "=f"(v.w)
        : "l"(p), "l"(pol));
    return v;
}

__global__ __launch_bounds__(BLOCK_THREADS, MIN_BLOCKS_SM)
void cbow_fused_kernel(const int*   __restrict__ context,    // [B, NCTX]
                       const int*   __restrict__ center,     // [B]
                       const int*   __restrict__ negatives,  // [B, NNEG]
                       const float* __restrict__ ctx_w,      // [V, 300]
                       const float* __restrict__ cen_w,      // [V, 300]
                       float*       __restrict__ out)
{
    const int warp = threadIdx.x >> 5;
    const int lane = threadIdx.x & 31;
    const int b    = blockIdx.x * WARPS_PER_BLOCK + warp;

    const unsigned long long pol_stream   = policy_evict_first();
    const unsigned long long pol_resident = policy_evict_last_half();

    // ---- all 31 indices for this b, one per lane ----
    int idx = 0;
    if (lane < NCTX)            idx = context[b * NCTX + lane];
    else if (lane == NCTX)      idx = center[b];
    else if (lane < NCTX + NSC) idx = negatives[b * NNEG + (lane - NCTX - 1)];

    const bool tail = (lane < NF4 - 64);   // lane < 11

    // ================= ctx mean, software-pipelined =================
    float4 cm0 = make_float4(0.f, 0.f, 0.f, 0.f);
    float4 cm1 = cm0;
    float4 cm2 = cm0;

    {
        int row0 = __shfl_sync(0xffffffffu, idx, 0);
        const float4* r = reinterpret_cast<const float4*>(ctx_w + (size_t)row0 * EMBED);
        float4 n0 = ldg_hint(r + lane,      pol_stream);
        float4 n1 = ldg_hint(r + lane + 32, pol_stream);
        float4 n2 = tail ? ldg_hint(r + lane + 64, pol_stream)
                         : make_float4(0.f, 0.f, 0.f, 0.f);

        #pragma unroll
        for (int c = 0; c < NCTX; ++c) {
            float4 a0 = n0, a1 = n1, a2 = n2;
            if (c + 1 < NCTX) {
                int row = __shfl_sync(0xffffffffu, idx, c + 1);
                const float4* rn = reinterpret_cast<const float4*>(ctx_w + (size_t)row * EMBED);
                n0 = ldg_hint(rn + lane,      pol_stream);
                n1 = ldg_hint(rn + lane + 32, pol_stream);
                if (tail) n2 = ldg_hint(rn + lane + 64, pol_stream);
            }
            cm0.x += a0.x; cm0.y += a0.y; cm0.z += a0.z; cm0.w += a0.w;
            cm1.x += a1.x; cm1.y += a1.y; cm1.z += a1.z; cm1.w += a1.w;
            if (tail) {
                cm2.x += a2.x; cm2.y += a2.y; cm2.z += a2.z; cm2.w += a2.w;
            }
        }
    }
    const float inv_c = 1.0f / (float)NCTX;
    cm0.x *= inv_c; cm0.y *= inv_c; cm0.z *= inv_c; cm0.w *= inv_c;
    cm1.x *= inv_c; cm1.y *= inv_c; cm1.z *= inv_c; cm1.w *= inv_c;
    cm2.x *= inv_c; cm2.y *= inv_c; cm2.z *= inv_c; cm2.w *= inv_c;

    // ================= 21 scores, software-pipelined =================
    __shared__ float sh_s[WARPS_PER_BLOCK][NSC];

    {
        int row0 = __shfl_sync(0xffffffffu, idx, NCTX);
        const float4* r = reinterpret_cast<const float4*>(cen_w + (size_t)row0 * EMBED);
        float4 n0 = ldg_hint(r + lane,      pol_resident);
        float4 n1 = ldg_hint(r + lane + 32, pol_resident);
        float4 n2 = tail ? ldg_hint(r + lane + 64, pol_resident)
                         : make_float4(0.f, 0.f, 0.f, 0.f);

        #pragma unroll
        for (int t = 0; t < NSC; ++t) {
            float4 a0 = n0, a1 = n1, a2 = n2;
            if (t + 1 < NSC) {
                int row = __shfl_sync(0xffffffffu, idx, NCTX + t + 1);
                const float4* rn = reinterpret_cast<const float4*>(cen_w + (size_t)row * EMBED);
                n0 = ldg_hint(rn + lane,      pol_resident);
                n1 = ldg_hint(rn + lane + 32, pol_resident);
                if (tail) n2 = ldg_hint(rn + lane + 64, pol_resident);
            }
            float s = dot4(a0, cm0) + dot4(a1, cm1);
            if (tail) s += dot4(a2, cm2);
            #pragma unroll
            for (int off = 16; off > 0; off >>= 1)
                s += __shfl_xor_sync(0xffffffffu, s, off);
            if (lane == 0) sh_s[warp][t] = s;
        }
    }
    __syncwarp();

    // ---- parallel log-sigmoids: one per lane ----
    float l = 0.0f;
    if (lane < NSC) {
        float s = sh_s[warp][lane];
        l = log_sigmoid(lane == 0 ? s : -s);
    }
    #pragma unroll
    for (int off = 16; off > 0; off >>= 1)
        l += __shfl_xor_sync(0xffffffffu, l, off);

    __shared__ float sdata[WARPS_PER_BLOCK];
    if (lane == 0) sdata[warp] = -l;
    __syncthreads();

    // ---- fused grid reduction: last block finalizes ----
    if (threadIdx.x == 0) {
        float tot = 0.f;
        #pragma unroll
        for (int i = 0; i < WARPS_PER_BLOCK; ++i) tot += sdata[i];

        atomicAdd(&g_sum, tot);
        __threadfence();
        unsigned prev = atomicAdd(&g_arrived, 1u);
        if (prev == GRID_BLOCKS - 1) {
            float total = g_sum;
            out[0] = total / (float)BATCH;
            g_sum = 0.0f;
            __threadfence();
            g_arrived = 0u;
        }
    }
}

extern "C" void kernel_launch(void* const* d_in, const int* in_sizes, int n_in,
                              void* d_out, int out_size)
{
    const int*   context   = (const int*)  d_in[0];
    const int*   center    = (const int*)  d_in[1];
    const int*   negatives = (const int*)  d_in[2];
    const float* ctx_w     = (const float*)d_in[3];
    const float* cen_w     = (const float*)d_in[4];
    float*       out       = (float*)d_out;

    cbow_fused_kernel<<<GRID_BLOCKS, BLOCK_THREADS>>>(
        context, center, negatives, ctx_w, cen_w, out);
}

// round 15
// speedup vs baseline: 1.1762x; 1.0679x over previous
#include <cuda_runtime.h>
#include <cstdint>

#define BATCH 16384
#define EMBED 300
#define ROW_BYTES 1200
#define NCTX  10
#define NNEG  20
#define NSC   (1 + NNEG)     // 21 scores
#define NROWS (NCTX + NSC)   // 31 rows per batch element
#define NF4   75
#define CHUNK 2
#define NCHUNKS ((NROWS + CHUNK - 1) / CHUNK)   // 16 (last chunk = 1 row)
#define WARPS_PER_BLOCK 8
#define BLOCK_THREADS   (WARPS_PER_BLOCK * 32)
#define GRID_BLOCKS     (BATCH / WARPS_PER_BLOCK)   // 2048
#define MIN_BLOCKS_SM   5

// fused-reduction state (zero-init .bss; last block resets for graph replays)
__device__ float        g_sum;
__device__ unsigned int g_arrived;

__device__ __forceinline__ float log_sigmoid(float x) {
    return fminf(x, 0.0f) - log1pf(__expf(-fabsf(x)));
}
__device__ __forceinline__ float dot4(float4 a, float4 b) {
    return a.x * b.x + a.y * b.y + a.z * b.z + a.w * b.w;
}

__device__ __forceinline__ unsigned long long policy_evict_first() {
    unsigned long long p;
    asm("createpolicy.fractional.L2::evict_first.b64 %0, 1.0;" : "=l"(p));
    return p;
}
__device__ __forceinline__ unsigned long long policy_evict_last_half() {
    unsigned long long p;
    asm("createpolicy.fractional.L2::evict_last.b64 %0, 0.5;" : "=l"(p));
    return p;
}

// 16-byte async copy gmem -> smem, L1-bypass (.cg), with L2 policy
__device__ __forceinline__ void cp16(unsigned int dst, const void* src,
                                     unsigned long long pol) {
    asm volatile("cp.async.cg.shared.global.L2::cache_hint [%0], [%1], 16, %2;"
                 :: "r"(dst), "l"(src), "l"(pol));
}
__device__ __forceinline__ void cp_commit() {
    asm volatile("cp.async.commit_group;");
}
__device__ __forceinline__ void cp_wait1() {
    asm volatile("cp.async.wait_group 1;");
}
__device__ __forceinline__ void cp_wait0() {
    asm volatile("cp.async.wait_group 0;");
}

__global__ __launch_bounds__(BLOCK_THREADS, MIN_BLOCKS_SM)
void cbow_fused_kernel(const int*   __restrict__ context,    // [B, NCTX]
                       const int*   __restrict__ center,     // [B]
                       const int*   __restrict__ negatives,  // [B, NNEG]
                       const float* __restrict__ ctx_w,      // [V, 300]
                       const float* __restrict__ cen_w,      // [V, 300]
                       float*       __restrict__ out)
{
    // per-warp double buffer: [warp][buf 0/1][row 0/1][1200 B]
    __shared__ __align__(16) char sbuf[WARPS_PER_BLOCK][2][CHUNK][ROW_BYTES];
    __shared__ float sh_s[WARPS_PER_BLOCK][NSC];
    __shared__ float sdata[WARPS_PER_BLOCK];

    const int warp = threadIdx.x >> 5;
    const int lane = threadIdx.x & 31;
    const int b    = blockIdx.x * WARPS_PER_BLOCK + warp;
    const bool tail = (lane < NF4 - 64);   // lane < 11

    const unsigned long long pol_stream   = policy_evict_first();
    const unsigned long long pol_resident = policy_evict_last_half();

    // ---- all 31 indices for this b, one per lane ----
    int idx = 0;
    if (lane < NCTX)        idx = context[b * NCTX + lane];
    else if (lane == NCTX)  idx = center[b];
    else if (lane < NROWS)  idx = negatives[b * NNEG + (lane - NCTX - 1)];

    const unsigned int s_warp =
        (unsigned int)__cvta_generic_to_shared(&sbuf[warp][0][0][0]);

    // issue one chunk (rows k*CHUNK .. ) into buffer `buf`
    auto issue_chunk = [&](int k, int buf) {
        #pragma unroll
        for (int j = 0; j < CHUNK; ++j) {
            int r = k * CHUNK + j;
            if (r < NROWS) {
                int row = __shfl_sync(0xffffffffu, idx, r);
                const char* src = (const char*)((r < NCTX ? ctx_w : cen_w)
                                                + (size_t)row * EMBED);
                unsigned long long pol = (r < NCTX) ? pol_stream : pol_resident;
                unsigned int dst = s_warp
                    + (unsigned int)(buf * (CHUNK * ROW_BYTES) + j * ROW_BYTES);
                cp16(dst + lane * 16,        src + lane * 16,        pol);
                cp16(dst + 512 + lane * 16,  src + 512 + lane * 16,  pol);
                if (tail)
                    cp16(dst + 1024 + lane * 16, src + 1024 + lane * 16, pol);
            }
        }
        cp_commit();
    };

    float4 cm0 = make_float4(0.f, 0.f, 0.f, 0.f);
    float4 cm1 = cm0;
    float4 cm2 = cm0;

    issue_chunk(0, 0);
    issue_chunk(1, 1);

    for (int k = 0; k < NCHUNKS; ++k) {
        if (k < NCHUNKS - 1) cp_wait1(); else cp_wait0();

        const int buf = k & 1;
        #pragma unroll
        for (int j = 0; j < CHUNK; ++j) {
            int r = k * CHUNK + j;
            if (r < NROWS) {
                const float4* p = reinterpret_cast<const float4*>(
                    &sbuf[warp][buf][j][0]);
                float4 a0 = p[lane];
                float4 a1 = p[lane + 32];
                if (r < NCTX) {
                    cm0.x += a0.x; cm0.y += a0.y; cm0.z += a0.z; cm0.w += a0.w;
                    cm1.x += a1.x; cm1.y += a1.y; cm1.z += a1.z; cm1.w += a1.w;
                    if (tail) {
                        float4 a2 = p[lane + 64];
                        cm2.x += a2.x; cm2.y += a2.y; cm2.z += a2.z; cm2.w += a2.w;
                    }
                } else {
                    float s = dot4(a0, cm0) + dot4(a1, cm1);
                    if (tail) {
                        float4 a2 = p[lane + 64];
                        s += dot4(a2, cm2);
                    }
                    #pragma unroll
                    for (int off = 16; off > 0; off >>= 1)
                        s += __shfl_xor_sync(0xffffffffu, s, off);
                    if (lane == 0) sh_s[warp][r - NCTX] = s;
                }
            }
        }

        if (k + 2 < NCHUNKS) issue_chunk(k + 2, buf);
    }
    __syncwarp();

    // ---- parallel log-sigmoids (scores carry the /NCTX scale here) ----
    float l = 0.0f;
    if (lane < NSC) {
        float s = sh_s[warp][lane] * (1.0f / (float)NCTX);
        l = log_sigmoid(lane == 0 ? s : -s);
    }
    #pragma unroll
    for (int off = 16; off > 0; off >>= 1)
        l += __shfl_xor_sync(0xffffffffu, l, off);

    if (lane == 0) sdata[warp] = -l;
    __syncthreads();

    // ---- fused grid reduction: last block finalizes ----
    if (threadIdx.x == 0) {
        float tot = 0.f;
        #pragma unroll
        for (int i = 0; i < WARPS_PER_BLOCK; ++i) tot += sdata[i];

        atomicAdd(&g_sum, tot);
        __threadfence();
        unsigned prev = atomicAdd(&g_arrived, 1u);
        if (prev == GRID_BLOCKS - 1) {
            float total = g_sum;
            out[0] = total / (float)BATCH;
            g_sum = 0.0f;
            __threadfence();
            g_arrived = 0u;
        }
    }
}

extern "C" void kernel_launch(void* const* d_in, const int* in_sizes, int n_in,
                              void* d_out, int out_size)
{
    const int*   context   = (const int*)  d_in[0];
    const int*   center    = (const int*)  d_in[1];
    const int*   negatives = (const int*)  d_in[2];
    const float* ctx_w     = (const float*)d_in[3];
    const float* cen_w     = (const float*)d_in[4];
    float*       out       = (float*)d_out;

    cbow_fused_kernel<<<GRID_BLOCKS, BLOCK_THREADS>>>(
        context, center, negatives, ctx_w, cen_w, out);
}